// round 10
// baseline (speedup 1.0000x reference)
#include <cuda_runtime.h>
#include <cuda_bf16.h>

#define NBINS_H  65536
#define WINLO    61440        // smem-aggregated coarse window [WINLO, NBINS_H)
#define WINSZ    4096
#define CAP      4096
#define MAXC     300
#define TOPN     100
#define MAXN     1000448
#define NW       5            // ceil(300/64)

// ---- scratch (device globals; zero-init at load; every launch re-zeroes) ----
__device__ unsigned int       g_keys[MAXN];   // ~bits(m); 0xFFFFFFFF invalid
__device__ unsigned int       g_hist[NBINS_H];
__device__ unsigned int       g_count;
__device__ int                g_thrbin;
__device__ unsigned long long g_cand[CAP];

// hbin: ascending in f = 1-m  ==> descending in score m. ~512 sub-bins/octave.
__device__ __forceinline__ int hist_bin(float m) {
    float f = 1.0f - m;                       // >= 0, < 0.9 for valid m > 0.1
    return (int)(__float_as_uint(f) >> 14);   // <= 64920 < NBINS_H
}

// ---------------- shared box decode ----------------
__device__ __forceinline__ void decode_core(
    float x1, float y1, float x2, float y2,
    float4 d, float W, float H,
    float& bx1, float& by1, float& bx2, float& by2)
{
    float w  = x2 - x1 + 1.0f;
    float h  = y2 - y1 + 1.0f;
    float cx = x1 + 0.5f*(w - 1.0f);
    float cy = y1 + 0.5f*(h - 1.0f);
    float dx = d.x*0.1f, dy = d.y*0.1f, dw = d.z*0.2f, dh = d.w*0.2f;
    float pcx = dx*w + cx;
    float pcy = dy*h + cy;
    float pw  = expf(dw)*w;
    float ph  = expf(dh)*h;
    bx1 = fminf(fmaxf(pcx - 0.5f*(pw - 1.0f), 0.0f), W);
    by1 = fminf(fmaxf(pcy - 0.5f*(ph - 1.0f), 0.0f), H);
    bx2 = fminf(fmaxf(pcx + 0.5f*(pw - 1.0f), 0.0f), W);
    by2 = fminf(fmaxf(pcy + 0.5f*(ph - 1.0f), 0.0f), H);
}

// ---- K1: 4 rois/thread; smem window hist for bulk, direct atomics for top ----
__global__ void __launch_bounds__(256) k1_score(
    const float* __restrict__ cls,
    const float* __restrict__ bbox,
    const float* __restrict__ rois,
    const float* __restrict__ iminfo,
    int ngrp, int n)
{
    __shared__ unsigned int sh[WINSZ];
    int tid = threadIdx.x;

    #pragma unroll
    for (int j = tid; j < WINSZ/4; j += 256)
        reinterpret_cast<uint4*>(sh)[j] = make_uint4(0,0,0,0);
    __syncthreads();

    int g = blockIdx.x*blockDim.x + tid;
    if (g < ngrp) {
        int base = g * 4;
        bool full = (base + 4 <= n);

        float c[20], r[20];
        if (full) {
            const float4* c4 = reinterpret_cast<const float4*>(cls)  + (size_t)g*5;
            const float4* r4 = reinterpret_cast<const float4*>(rois) + (size_t)g*5;
            #pragma unroll
            for (int q = 0; q < 5; q++) {
                float4 t = c4[q];
                c[4*q]=t.x; c[4*q+1]=t.y; c[4*q+2]=t.z; c[4*q+3]=t.w;
            }
            #pragma unroll
            for (int q = 0; q < 5; q++) {
                float4 t = r4[q];
                r[4*q]=t.x; r[4*q+1]=t.y; r[4*q+2]=t.z; r[4*q+3]=t.w;
            }
        } else {
            #pragma unroll
            for (int q = 0; q < 4; q++) {
                if (base + q < n) {
                    #pragma unroll
                    for (int e = 0; e < 5; e++) {
                        c[q*5+e] = cls [(size_t)(base+q)*5 + e];
                        r[q*5+e] = rois[(size_t)(base+q)*5 + e];
                    }
                }
            }
        }

        float W = iminfo[1] - 1.0f, H = iminfo[0] - 1.0f;
        unsigned int outk[4];

        #pragma unroll
        for (int q = 0; q < 4; q++) {
            unsigned int key = 0xFFFFFFFFu;   // invalid marker
            if (base + q < n) {
                float s0=c[q*5], s1=c[q*5+1], s2=c[q*5+2], s3=c[q*5+3], s4=c[q*5+4];
                float m = s1; int a = 1;
                if (s2 > m) { m = s2; a = 2; }
                if (s3 > m) { m = s3; a = 3; }
                if (s4 > m) { m = s4; a = 4; }
                if ((1.0f - s0 >= 0.2f) && (m > 0.1f)) {
                    float4 d = *reinterpret_cast<const float4*>(
                        bbox + (size_t)(base+q)*20 + a*4);
                    float bx1, by1, bx2, by2;
                    decode_core(r[q*5+1], r[q*5+2], r[q*5+3], r[q*5+4],
                                d, W, H, bx1, by1, bx2, by2);
                    float bw = bx2 - bx1 + 1.0f;
                    float bh = by2 - by1 + 1.0f;
                    if (bw >= 6.0f || bh >= 6.0f) {
                        key = ~__float_as_uint(m);
                        int hb = hist_bin(m);
                        if (hb >= WINLO) atomicAdd(&sh[hb - WINLO], 1u);
                        else             atomicAdd(&g_hist[hb], 1u); // rare, spread
                    }
                }
            }
            outk[q] = key;
        }

        if (full) {
            *reinterpret_cast<uint4*>(g_keys + base) =
                make_uint4(outk[0], outk[1], outk[2], outk[3]);
        } else {
            #pragma unroll
            for (int q = 0; q < 4; q++)
                if (base + q < n) g_keys[base + q] = outk[q];
        }
    }
    __syncthreads();

    #pragma unroll
    for (int j = tid; j < WINSZ; j += 256) {
        unsigned int v = sh[j];
        if (v) atomicAdd(&g_hist[WINLO + j], v);
    }
}

// -- K2: smallest hbin thr with count(hbin<=thr) >= 300 (prefix scan); zero hist --
__global__ void k2_thresh() {
    __shared__ unsigned int part[1024];
    __shared__ int thr_sh;
    int t = threadIdx.x;
    if (t == 0) thr_sh = NBINS_H - 1;     // default: collect all valid

    const int CH = NBINS_H / 1024;        // 64 bins per thread
    unsigned int s = 0;
    int cbase = t * CH;
    #pragma unroll 8
    for (int b = 0; b < CH; b++) s += g_hist[cbase + b];
    part[t] = s;
    __syncthreads();

    // inclusive PREFIX scan (ascending hbin = descending score)
    #pragma unroll
    for (int d = 1; d < 1024; d <<= 1) {
        unsigned int v = part[t] + ((t >= d) ? part[t - d] : 0u);
        __syncthreads();
        part[t] = v;
        __syncthreads();
    }

    bool owner = (part[t] >= (unsigned)MAXC) &&
                 (t == 0 || part[t - 1] < (unsigned)MAXC);
    if (owner) {
        unsigned int cum = (t == 0) ? 0u : part[t - 1];
        for (int b = cbase; b < cbase + CH; b++) {
            cum += g_hist[b];
            if (cum >= (unsigned)MAXC) { thr_sh = b; break; }
        }
    }
    __syncthreads();

    // zero 65536-bin histogram for next replay (16 uint4 per thread)
    uint4* h4 = reinterpret_cast<uint4*>(g_hist);
    #pragma unroll
    for (int j = 0; j < NBINS_H/4/1024; j++)
        h4[t*(NBINS_H/4/1024) + j] = make_uint4(0,0,0,0);

    if (t == 0) g_thrbin = thr_sh;
}

// ------ K3: collect candidates with hbin <= thr, 16 rois/thread ------
__global__ void k3_collect(int ngrp16, int n) {
    int g = blockIdx.x*blockDim.x + threadIdx.x;
    if (g >= ngrp16) return;
    int base = g * 16;
    uint4 v[4];
    #pragma unroll
    for (int p = 0; p < 4; p++)
        v[p] = reinterpret_cast<const uint4*>(g_keys)[g*4 + p];
    int thr = g_thrbin;
    #pragma unroll
    for (int p = 0; p < 4; p++) {
        unsigned int kk[4] = {v[p].x, v[p].y, v[p].z, v[p].w};
        #pragma unroll
        for (int l = 0; l < 4; l++) {
            unsigned int key = kk[l];
            int i = base + p*4 + l;
            if (key != 0xFFFFFFFFu && i < n) {
                float m = __uint_as_float(~key);
                if (hist_bin(m) <= thr) {
                    unsigned int pos = atomicAdd(&g_count, 1u);
                    if (pos < CAP) {
                        g_cand[pos] = (((unsigned long long)key) << 32) |
                                      (unsigned int)i;
                    }
                }
            }
        }
    }
}

// -- K4: rank-sort (M~305) + decode + bitmatrix + word-walk + output + reset --
#define K4T 512

__global__ void k4_final(const float* __restrict__ cls,
                         const float* __restrict__ bbox,
                         const float* __restrict__ rois,
                         const float* __restrict__ iminfo,
                         float* __restrict__ out)
{
    __shared__ unsigned long long keys[CAP];
    __shared__ unsigned long long skey[MAXC];
    __shared__ float bx[MAXC][4];
    __shared__ float pr[MAXC][5];
    __shared__ float area[MAXC];
    __shared__ unsigned long long srm[MAXC * NW];
    __shared__ int kept[TOPN];
    __shared__ int nkept;

    int tid = threadIdx.x;
    int M = (int)min(g_count, (unsigned int)CAP);
    int K = min(M, MAXC);

    for (int t = tid; t < M; t += K4T) keys[t] = g_cand[t];
    __syncthreads();

    // rank-sort (M expected ~305): asc key == (score desc, idx asc)
    for (int t = tid; t < M; t += K4T) {
        unsigned long long k = keys[t];
        int r = 0;
        for (int j = 0; j < M; j++) r += (keys[j] < k);
        if (r < MAXC) skey[r] = k;
    }
    __syncthreads();

    float W = iminfo[1] - 1.0f, H = iminfo[0] - 1.0f;

    if (tid < K) {
        int t = tid;
        int i = (int)(unsigned int)(skey[t] & 0xFFFFFFFFULL);
        const float* c = cls + (size_t)i*5;
        float c0=c[0], c1=c[1], c2=c[2], c3=c[3], c4=c[4];
        pr[t][0]=c0; pr[t][1]=c1; pr[t][2]=c2; pr[t][3]=c3; pr[t][4]=c4;
        float m = c1; int a = 1;
        if (c2 > m) { m = c2; a = 2; }
        if (c3 > m) { m = c3; a = 3; }
        if (c4 > m) { m = c4; a = 4; }
        float4 d = *reinterpret_cast<const float4*>(bbox + (size_t)i*20 + a*4);
        float bx1, by1, bx2, by2;
        decode_core(rois[(size_t)i*5+1], rois[(size_t)i*5+2],
                    rois[(size_t)i*5+3], rois[(size_t)i*5+4],
                    d, W, H, bx1, by1, bx2, by2);
        bx[t][0]=bx1; bx[t][1]=by1; bx[t][2]=bx2; bx[t][3]=by2;
        area[t] = (bx2 - bx1) * (by2 - by1);
    }
    __syncthreads();

    if (tid < K) {
        int i = tid;
        float ax1=bx[i][0], ay1=bx[i][1], ax2=bx[i][2], ay2=bx[i][3], aa=area[i];
        #pragma unroll
        for (int w = 0; w < NW; w++) {
            unsigned long long bits = 0ULL;
            int j0 = max(i + 1, w*64);
            int j1 = min(K, w*64 + 64);
            for (int j = j0; j < j1; j++) {
                float4 b4 = *reinterpret_cast<const float4*>(&bx[j][0]);
                float lx = fmaxf(ax1, b4.x);
                float ly = fmaxf(ay1, b4.y);
                float rx = fminf(ax2, b4.z);
                float ry = fminf(ay2, b4.w);
                float iw = fmaxf(rx - lx, 0.0f);
                float ih = fmaxf(ry - ly, 0.0f);
                float inter = iw * ih;
                float iou = inter / (aa + area[j] - inter);
                if (iou > 0.5f) bits |= 1ULL << (j - w*64);
            }
            srm[i*NW + w] = bits;
        }
    }
    __syncthreads();

    if (tid == 0) {
        unsigned long long sup1=0, sup2=0, sup3=0, sup4=0;
        int cnt = 0;

        #define WALK_WORD(WD, SUPIN, ORS)                                     \
        if (cnt < TOPN && K > (WD)*64) {                                      \
            int nb = K - (WD)*64; if (nb > 64) nb = 64;                       \
            unsigned long long alive =                                        \
                ((nb >= 64) ? ~0ULL : ((1ULL << nb) - 1ULL)) & ~(SUPIN);      \
            while (alive && cnt < TOPN) {                                     \
                int b = __ffsll((long long)alive) - 1;                        \
                int i = (WD)*64 + b;                                          \
                kept[cnt++] = i;                                              \
                alive &= ~srm[i*NW + (WD)];                                   \
                alive &= ~(1ULL << b);                                        \
                ORS                                                           \
            }                                                                 \
        }

        WALK_WORD(0, 0ULL,
            { sup1 |= srm[i*NW+1]; sup2 |= srm[i*NW+2];
              sup3 |= srm[i*NW+3]; sup4 |= srm[i*NW+4]; })
        WALK_WORD(1, sup1,
            { sup2 |= srm[i*NW+2]; sup3 |= srm[i*NW+3]; sup4 |= srm[i*NW+4]; })
        WALK_WORD(2, sup2,
            { sup3 |= srm[i*NW+3]; sup4 |= srm[i*NW+4]; })
        WALK_WORD(3, sup3,
            { sup4 |= srm[i*NW+4]; })
        WALK_WORD(4, sup4, { })
        #undef WALK_WORD

        nkept = cnt;
    }
    __syncthreads();

    for (int t = tid; t < TOPN*10; t += K4T) out[t] = 0.0f;
    __syncthreads();
    int nk = nkept;
    for (int r = tid; r < nk; r += K4T) {
        int i = kept[r];
        float* o = out + r*10;
        o[0] = 0.0f;
        o[1] = bx[i][0]; o[2] = bx[i][1]; o[3] = bx[i][2]; o[4] = bx[i][3];
        o[5] = pr[i][0]; o[6] = pr[i][1]; o[7] = pr[i][2];
        o[8] = pr[i][3]; o[9] = pr[i][4];
    }

    if (tid == 0) g_count = 0u;   // reset for next graph replay
}

// ---------------- launch ----------------
extern "C" void kernel_launch(void* const* d_in, const int* in_sizes, int n_in,
                              void* d_out, int out_size)
{
    const float* cls    = (const float*)d_in[0];
    const float* bbox   = (const float*)d_in[1];
    const float* rois   = (const float*)d_in[2];
    const float* iminfo = (const float*)d_in[3];
    float* out = (float*)d_out;
    int n = in_sizes[0] / 5;
    if (n > MAXN) n = MAXN;

    int ngrp4  = (n + 3) / 4;
    int ngrp16 = (n + 15) / 16;

    k1_score  <<<(ngrp4 + 255)/256, 256>>>(cls, bbox, rois, iminfo, ngrp4, n);
    k2_thresh <<<1, 1024>>>();
    k3_collect<<<(ngrp16 + 255)/256, 256>>>(ngrp16, n);
    k4_final  <<<1, K4T>>>(cls, bbox, rois, iminfo, out);
}

// round 11
// speedup vs baseline: 1.3509x; 1.3509x over previous
#include <cuda_runtime.h>
#include <cuda_bf16.h>

#define NBINS    2048
#define CAP      6144         // 48KB smem in k4a; M (score ties) ~4000
#define MAXC     300
#define TOPN     100
#define MAXN     1000448
#define NW       5            // ceil(300/64)

// ---- scratch (device globals; zero-init at load; every launch re-zeroes) ----
__device__ unsigned int       g_keys[MAXN];   // ~bits(m); 0xFFFFFFFF invalid
__device__ unsigned int       g_hist[NBINS];
__device__ unsigned int       g_count;
__device__ unsigned int       g_blkdone;
__device__ int                g_thrbin;
__device__ unsigned long long g_cand[CAP];
__device__ unsigned long long g_skey[MAXC];   // top-300 sorted keys
__device__ int                g_K;

// relative bin: ascending in f = 1-m (descending in score). Ties at m==1 -> bin 0.
__device__ __forceinline__ int hist_bin(float m) {
    float f = 1.0f - m;                       // f in [0, 0.9) for valid m
    int b = (int)(__float_as_uint(f) >> 19);  // < 2048 for f < 1.0
    return min(b, NBINS - 1);
}

// ---------------- shared box decode ----------------
__device__ __forceinline__ void decode_core(
    float x1, float y1, float x2, float y2,
    float4 d, float W, float H,
    float& bx1, float& by1, float& bx2, float& by2)
{
    float w  = x2 - x1 + 1.0f;
    float h  = y2 - y1 + 1.0f;
    float cx = x1 + 0.5f*(w - 1.0f);
    float cy = y1 + 0.5f*(h - 1.0f);
    float dx = d.x*0.1f, dy = d.y*0.1f, dw = d.z*0.2f, dh = d.w*0.2f;
    float pcx = dx*w + cx;
    float pcy = dy*h + cy;
    float pw  = expf(dw)*w;
    float ph  = expf(dh)*h;
    bx1 = fminf(fmaxf(pcx - 0.5f*(pw - 1.0f), 0.0f), W);
    by1 = fminf(fmaxf(pcy - 0.5f*(ph - 1.0f), 0.0f), H);
    bx2 = fminf(fmaxf(pcx + 0.5f*(pw - 1.0f), 0.0f), W);
    by2 = fminf(fmaxf(pcy + 0.5f*(ph - 1.0f), 0.0f), H);
}

// ---- K1: 4 rois/thread; smem hist; LAST BLOCK computes threshold + zeroes ----
__global__ void __launch_bounds__(256) k1_score(
    const float* __restrict__ cls,
    const float* __restrict__ bbox,
    const float* __restrict__ rois,
    const float* __restrict__ iminfo,
    int ngrp, int n)
{
    __shared__ unsigned int sh[NBINS];
    int tid = threadIdx.x;

    #pragma unroll
    for (int j = tid; j < NBINS/4; j += 256)
        reinterpret_cast<uint4*>(sh)[j] = make_uint4(0,0,0,0);
    __syncthreads();

    int g = blockIdx.x*blockDim.x + tid;
    if (g < ngrp) {
        int base = g * 4;
        bool full = (base + 4 <= n);

        float c[20], r[20];
        if (full) {
            const float4* c4 = reinterpret_cast<const float4*>(cls)  + (size_t)g*5;
            const float4* r4 = reinterpret_cast<const float4*>(rois) + (size_t)g*5;
            #pragma unroll
            for (int q = 0; q < 5; q++) {
                float4 t = c4[q];
                c[4*q]=t.x; c[4*q+1]=t.y; c[4*q+2]=t.z; c[4*q+3]=t.w;
            }
            #pragma unroll
            for (int q = 0; q < 5; q++) {
                float4 t = r4[q];
                r[4*q]=t.x; r[4*q+1]=t.y; r[4*q+2]=t.z; r[4*q+3]=t.w;
            }
        } else {
            #pragma unroll
            for (int q = 0; q < 4; q++) {
                if (base + q < n) {
                    #pragma unroll
                    for (int e = 0; e < 5; e++) {
                        c[q*5+e] = cls [(size_t)(base+q)*5 + e];
                        r[q*5+e] = rois[(size_t)(base+q)*5 + e];
                    }
                }
            }
        }

        float W = iminfo[1] - 1.0f, H = iminfo[0] - 1.0f;
        unsigned int outk[4];

        #pragma unroll
        for (int q = 0; q < 4; q++) {
            unsigned int key = 0xFFFFFFFFu;   // invalid marker
            if (base + q < n) {
                float s0=c[q*5], s1=c[q*5+1], s2=c[q*5+2], s3=c[q*5+3], s4=c[q*5+4];
                float m = s1; int a = 1;
                if (s2 > m) { m = s2; a = 2; }
                if (s3 > m) { m = s3; a = 3; }
                if (s4 > m) { m = s4; a = 4; }
                if ((1.0f - s0 >= 0.2f) && (m > 0.1f)) {
                    float4 d = *reinterpret_cast<const float4*>(
                        bbox + (size_t)(base+q)*20 + a*4);
                    float bx1, by1, bx2, by2;
                    decode_core(r[q*5+1], r[q*5+2], r[q*5+3], r[q*5+4],
                                d, W, H, bx1, by1, bx2, by2);
                    float bw = bx2 - bx1 + 1.0f;
                    float bh = by2 - by1 + 1.0f;
                    if (bw >= 6.0f || bh >= 6.0f) {
                        key = ~__float_as_uint(m);
                        atomicAdd(&sh[hist_bin(m)], 1u);
                    }
                }
            }
            outk[q] = key;
        }

        if (full) {
            *reinterpret_cast<uint4*>(g_keys + base) =
                make_uint4(outk[0], outk[1], outk[2], outk[3]);
        } else {
            #pragma unroll
            for (int q = 0; q < 4; q++)
                if (base + q < n) g_keys[base + q] = outk[q];
        }
    }
    __syncthreads();

    // flush smem hist to global (atomics -> L2-coherent)
    #pragma unroll
    for (int j = tid; j < NBINS; j += 256) {
        unsigned int v = sh[j];
        if (v) atomicAdd(&g_hist[j], v);
    }

    // ---- last-block: threshold scan + hist zero (replaces k2 launch) ----
    __shared__ bool is_last;
    __threadfence();
    if (tid == 0)
        is_last = (atomicAdd(&g_blkdone, 1u) == gridDim.x - 1);
    __syncthreads();
    if (!is_last) return;

    __shared__ unsigned int part[256];
    {
        unsigned int s = 0;
        #pragma unroll
        for (int j = 0; j < NBINS/256; j++) s += g_hist[tid*(NBINS/256) + j];
        part[tid] = s;
    }
    __syncthreads();
    if (tid == 0) {
        unsigned int cum = 0;
        int thr = NBINS - 1;               // default: collect all valid
        for (int cch = 0; cch < 256; cch++) {
            if (cum + part[cch] >= (unsigned)MAXC) {
                int lo = cch * (NBINS/256);
                for (int b = lo; b < lo + (NBINS/256); b++) {
                    cum += g_hist[b];
                    if (cum >= (unsigned)MAXC) { thr = b; break; }
                }
                break;
            }
            cum += part[cch];
        }
        g_thrbin = thr;
        g_blkdone = 0u;                    // reset for next replay
    }
    __syncthreads();
    #pragma unroll
    for (int j = tid; j < NBINS/4; j += 256)
        reinterpret_cast<uint4*>(g_hist)[j] = make_uint4(0,0,0,0);
}

// ------ K3: collect candidates with hbin <= thr, 16 rois/thread ------
__global__ void k3_collect(int ngrp16, int n) {
    int g = blockIdx.x*blockDim.x + threadIdx.x;
    if (g >= ngrp16) return;
    int base = g * 16;
    uint4 v[4];
    #pragma unroll
    for (int p = 0; p < 4; p++)
        v[p] = reinterpret_cast<const uint4*>(g_keys)[g*4 + p];
    int thr = g_thrbin;
    #pragma unroll
    for (int p = 0; p < 4; p++) {
        unsigned int kk[4] = {v[p].x, v[p].y, v[p].z, v[p].w};
        #pragma unroll
        for (int l = 0; l < 4; l++) {
            unsigned int key = kk[l];
            int i = base + p*4 + l;
            if (key != 0xFFFFFFFFu && i < n) {
                float m = __uint_as_float(~key);
                if (hist_bin(m) <= thr) {
                    unsigned int pos = atomicAdd(&g_count, 1u);
                    if (pos < CAP) {
                        g_cand[pos] = (((unsigned long long)key) << 32) |
                                      (unsigned int)i;
                    }
                }
            }
        }
    }
}

// ---------- K4a: multi-block rank-sort -> g_skey[0..min(M,300)) ----------
#define K4AB 32    // blocks
#define K4AT 256   // threads per block

__global__ void k4a_rank() {
    __shared__ unsigned long long keys[CAP];   // 48KB
    int tid = threadIdx.x;
    int M = (int)min(g_count, (unsigned int)CAP);

    for (int t = tid; t < M; t += K4AT) keys[t] = g_cand[t];
    __syncthreads();

    int chunk = (M + K4AB - 1) / K4AB;           // <=192 for CAP=6144
    int idx = blockIdx.x * chunk + tid;
    if (tid < chunk && idx < M) {
        unsigned long long k = keys[idx];
        int r = 0;
        for (int j = 0; j < M; j++) r += (keys[j] < k);
        if (r < MAXC) g_skey[r] = k;             // unique keys -> unique ranks
    }
    if (blockIdx.x == 0 && tid == 0) g_K = min(M, MAXC);
}

// ---------- K4b: decode + bitmatrix + word-walk NMS + output + reset ----------
#define K4BT 512

__global__ void k4b_final(const float* __restrict__ cls,
                          const float* __restrict__ bbox,
                          const float* __restrict__ rois,
                          const float* __restrict__ iminfo,
                          float* __restrict__ out)
{
    __shared__ float bx[MAXC][4];
    __shared__ float pr[MAXC][5];
    __shared__ float area[MAXC];
    __shared__ unsigned long long srm[MAXC * NW];
    __shared__ int kept[TOPN];
    __shared__ int nkept;

    int tid = threadIdx.x;
    int K = g_K;
    float W = iminfo[1] - 1.0f, H = iminfo[0] - 1.0f;

    if (tid < K) {
        int t = tid;
        int i = (int)(unsigned int)(g_skey[t] & 0xFFFFFFFFULL);
        const float* c = cls + (size_t)i*5;
        float c0=c[0], c1=c[1], c2=c[2], c3=c[3], c4=c[4];
        pr[t][0]=c0; pr[t][1]=c1; pr[t][2]=c2; pr[t][3]=c3; pr[t][4]=c4;
        float m = c1; int a = 1;
        if (c2 > m) { m = c2; a = 2; }
        if (c3 > m) { m = c3; a = 3; }
        if (c4 > m) { m = c4; a = 4; }
        float4 d = *reinterpret_cast<const float4*>(bbox + (size_t)i*20 + a*4);
        float bx1, by1, bx2, by2;
        decode_core(rois[(size_t)i*5+1], rois[(size_t)i*5+2],
                    rois[(size_t)i*5+3], rois[(size_t)i*5+4],
                    d, W, H, bx1, by1, bx2, by2);
        bx[t][0]=bx1; bx[t][1]=by1; bx[t][2]=bx2; bx[t][3]=by2;
        area[t] = (bx2 - bx1) * (by2 - by1);
    }
    __syncthreads();

    if (tid < K) {
        int i = tid;
        float ax1=bx[i][0], ay1=bx[i][1], ax2=bx[i][2], ay2=bx[i][3], aa=area[i];
        #pragma unroll
        for (int w = 0; w < NW; w++) {
            unsigned long long bits = 0ULL;
            int j0 = max(i + 1, w*64);
            int j1 = min(K, w*64 + 64);
            for (int j = j0; j < j1; j++) {
                float4 b4 = *reinterpret_cast<const float4*>(&bx[j][0]);
                float lx = fmaxf(ax1, b4.x);
                float ly = fmaxf(ay1, b4.y);
                float rx = fminf(ax2, b4.z);
                float ry = fminf(ay2, b4.w);
                float iw = fmaxf(rx - lx, 0.0f);
                float ih = fmaxf(ry - ly, 0.0f);
                float inter = iw * ih;
                float iou = inter / (aa + area[j] - inter);
                if (iou > 0.5f) bits |= 1ULL << (j - w*64);
            }
            srm[i*NW + w] = bits;
        }
    }
    __syncthreads();

    if (tid == 0) {
        unsigned long long sup1=0, sup2=0, sup3=0, sup4=0;
        int cnt = 0;

        #define WALK_WORD(WD, SUPIN, ORS)                                     \
        if (cnt < TOPN && K > (WD)*64) {                                      \
            int nb = K - (WD)*64; if (nb > 64) nb = 64;                       \
            unsigned long long alive =                                        \
                ((nb >= 64) ? ~0ULL : ((1ULL << nb) - 1ULL)) & ~(SUPIN);      \
            while (alive && cnt < TOPN) {                                     \
                int b = __ffsll((long long)alive) - 1;                        \
                int i = (WD)*64 + b;                                          \
                kept[cnt++] = i;                                              \
                alive &= ~srm[i*NW + (WD)];                                   \
                alive &= ~(1ULL << b);                                        \
                ORS                                                           \
            }                                                                 \
        }

        WALK_WORD(0, 0ULL,
            { sup1 |= srm[i*NW+1]; sup2 |= srm[i*NW+2];
              sup3 |= srm[i*NW+3]; sup4 |= srm[i*NW+4]; })
        WALK_WORD(1, sup1,
            { sup2 |= srm[i*NW+2]; sup3 |= srm[i*NW+3]; sup4 |= srm[i*NW+4]; })
        WALK_WORD(2, sup2,
            { sup3 |= srm[i*NW+3]; sup4 |= srm[i*NW+4]; })
        WALK_WORD(3, sup3,
            { sup4 |= srm[i*NW+4]; })
        WALK_WORD(4, sup4, { })
        #undef WALK_WORD

        nkept = cnt;
    }
    __syncthreads();

    for (int t = tid; t < TOPN*10; t += K4BT) out[t] = 0.0f;
    __syncthreads();
    int nk = nkept;
    for (int r = tid; r < nk; r += K4BT) {
        int i = kept[r];
        float* o = out + r*10;
        o[0] = 0.0f;
        o[1] = bx[i][0]; o[2] = bx[i][1]; o[3] = bx[i][2]; o[4] = bx[i][3];
        o[5] = pr[i][0]; o[6] = pr[i][1]; o[7] = pr[i][2];
        o[8] = pr[i][3]; o[9] = pr[i][4];
    }

    if (tid == 0) g_count = 0u;   // reset for next graph replay
}

// ---------------- launch ----------------
extern "C" void kernel_launch(void* const* d_in, const int* in_sizes, int n_in,
                              void* d_out, int out_size)
{
    const float* cls    = (const float*)d_in[0];
    const float* bbox   = (const float*)d_in[1];
    const float* rois   = (const float*)d_in[2];
    const float* iminfo = (const float*)d_in[3];
    float* out = (float*)d_out;
    int n = in_sizes[0] / 5;
    if (n > MAXN) n = MAXN;

    int ngrp4  = (n + 3) / 4;
    int ngrp16 = (n + 15) / 16;

    k1_score  <<<(ngrp4 + 255)/256, 256>>>(cls, bbox, rois, iminfo, ngrp4, n);
    k3_collect<<<(ngrp16 + 255)/256, 256>>>(ngrp16, n);
    k4a_rank  <<<K4AB, K4AT>>>();
    k4b_final <<<1, K4BT>>>(cls, bbox, rois, iminfo, out);
}

// round 12
// speedup vs baseline: 2.1133x; 1.5644x over previous
#include <cuda_runtime.h>
#include <cuda_bf16.h>

#define NBINS    2048
#define CAP      6144         // 48KB smem in k4a; M (score ties) ~4000
#define MAXC     300
#define TOPN     100
#define MAXN     1000448
#define NW       5            // ceil(300/64)

// ---- scratch (device globals; zero-init at load; every launch re-zeroes) ----
__device__ unsigned int       g_keys[MAXN];   // ~bits(m); 0xFFFFFFFF invalid
__device__ unsigned int       g_hist[NBINS];
__device__ unsigned int       g_count;
__device__ unsigned int       g_blkdone;      // k1 last-block counter
__device__ unsigned int       g_blkdone2;     // k4b last-block counter
__device__ int                g_thrbin;
__device__ unsigned long long g_cand[CAP];
__device__ unsigned long long g_skey[MAXC];   // top-300 sorted keys
__device__ int                g_K;
__device__ unsigned long long g_rm[MAXC * NW];

// relative bin: ascending in f = 1-m (descending in score). Ties at m==1 -> bin 0.
__device__ __forceinline__ int hist_bin(float m) {
    float f = 1.0f - m;
    int b = (int)(__float_as_uint(f) >> 19);
    return min(b, NBINS - 1);
}

// ---------------- shared box decode ----------------
__device__ __forceinline__ void decode_core(
    float x1, float y1, float x2, float y2,
    float4 d, float W, float H,
    float& bx1, float& by1, float& bx2, float& by2)
{
    float w  = x2 - x1 + 1.0f;
    float h  = y2 - y1 + 1.0f;
    float cx = x1 + 0.5f*(w - 1.0f);
    float cy = y1 + 0.5f*(h - 1.0f);
    float dx = d.x*0.1f, dy = d.y*0.1f, dw = d.z*0.2f, dh = d.w*0.2f;
    float pcx = dx*w + cx;
    float pcy = dy*h + cy;
    float pw  = expf(dw)*w;
    float ph  = expf(dh)*h;
    bx1 = fminf(fmaxf(pcx - 0.5f*(pw - 1.0f), 0.0f), W);
    by1 = fminf(fmaxf(pcy - 0.5f*(ph - 1.0f), 0.0f), H);
    bx2 = fminf(fmaxf(pcx + 0.5f*(pw - 1.0f), 0.0f), W);
    by2 = fminf(fmaxf(pcy + 0.5f*(ph - 1.0f), 0.0f), H);
}

// ---- K1: 4 rois/thread; smem hist; LAST BLOCK computes threshold + zeroes ----
__global__ void __launch_bounds__(256) k1_score(
    const float* __restrict__ cls,
    const float* __restrict__ bbox,
    const float* __restrict__ rois,
    const float* __restrict__ iminfo,
    int ngrp, int n)
{
    __shared__ unsigned int sh[NBINS];
    int tid = threadIdx.x;

    #pragma unroll
    for (int j = tid; j < NBINS/4; j += 256)
        reinterpret_cast<uint4*>(sh)[j] = make_uint4(0,0,0,0);
    __syncthreads();

    int g = blockIdx.x*blockDim.x + tid;
    if (g < ngrp) {
        int base = g * 4;
        bool full = (base + 4 <= n);

        float c[20], r[20];
        if (full) {
            const float4* c4 = reinterpret_cast<const float4*>(cls)  + (size_t)g*5;
            const float4* r4 = reinterpret_cast<const float4*>(rois) + (size_t)g*5;
            #pragma unroll
            for (int q = 0; q < 5; q++) {
                float4 t = c4[q];
                c[4*q]=t.x; c[4*q+1]=t.y; c[4*q+2]=t.z; c[4*q+3]=t.w;
            }
            #pragma unroll
            for (int q = 0; q < 5; q++) {
                float4 t = r4[q];
                r[4*q]=t.x; r[4*q+1]=t.y; r[4*q+2]=t.z; r[4*q+3]=t.w;
            }
        } else {
            #pragma unroll
            for (int q = 0; q < 4; q++) {
                if (base + q < n) {
                    #pragma unroll
                    for (int e = 0; e < 5; e++) {
                        c[q*5+e] = cls [(size_t)(base+q)*5 + e];
                        r[q*5+e] = rois[(size_t)(base+q)*5 + e];
                    }
                }
            }
        }

        float W = iminfo[1] - 1.0f, H = iminfo[0] - 1.0f;
        unsigned int outk[4];

        #pragma unroll
        for (int q = 0; q < 4; q++) {
            unsigned int key = 0xFFFFFFFFu;
            if (base + q < n) {
                float s0=c[q*5], s1=c[q*5+1], s2=c[q*5+2], s3=c[q*5+3], s4=c[q*5+4];
                float m = s1; int a = 1;
                if (s2 > m) { m = s2; a = 2; }
                if (s3 > m) { m = s3; a = 3; }
                if (s4 > m) { m = s4; a = 4; }
                if ((1.0f - s0 >= 0.2f) && (m > 0.1f)) {
                    float4 d = *reinterpret_cast<const float4*>(
                        bbox + (size_t)(base+q)*20 + a*4);
                    float bx1, by1, bx2, by2;
                    decode_core(r[q*5+1], r[q*5+2], r[q*5+3], r[q*5+4],
                                d, W, H, bx1, by1, bx2, by2);
                    float bw = bx2 - bx1 + 1.0f;
                    float bh = by2 - by1 + 1.0f;
                    if (bw >= 6.0f || bh >= 6.0f) {
                        key = ~__float_as_uint(m);
                        atomicAdd(&sh[hist_bin(m)], 1u);
                    }
                }
            }
            outk[q] = key;
        }

        if (full) {
            *reinterpret_cast<uint4*>(g_keys + base) =
                make_uint4(outk[0], outk[1], outk[2], outk[3]);
        } else {
            #pragma unroll
            for (int q = 0; q < 4; q++)
                if (base + q < n) g_keys[base + q] = outk[q];
        }
    }
    __syncthreads();

    #pragma unroll
    for (int j = tid; j < NBINS; j += 256) {
        unsigned int v = sh[j];
        if (v) atomicAdd(&g_hist[j], v);
    }

    // ---- last-block: threshold scan + hist zero ----
    __shared__ bool is_last;
    __threadfence();
    if (tid == 0)
        is_last = (atomicAdd(&g_blkdone, 1u) == gridDim.x - 1);
    __syncthreads();
    if (!is_last) return;

    __shared__ unsigned int part[256];
    {
        unsigned int s = 0;
        #pragma unroll
        for (int j = 0; j < NBINS/256; j++) s += g_hist[tid*(NBINS/256) + j];
        part[tid] = s;
    }
    __syncthreads();
    if (tid == 0) {
        unsigned int cum = 0;
        int thr = NBINS - 1;
        for (int cch = 0; cch < 256; cch++) {
            if (cum + part[cch] >= (unsigned)MAXC) {
                int lo = cch * (NBINS/256);
                for (int b = lo; b < lo + (NBINS/256); b++) {
                    cum += g_hist[b];
                    if (cum >= (unsigned)MAXC) { thr = b; break; }
                }
                break;
            }
            cum += part[cch];
        }
        g_thrbin = thr;
        g_blkdone = 0u;
    }
    __syncthreads();
    #pragma unroll
    for (int j = tid; j < NBINS/4; j += 256)
        reinterpret_cast<uint4*>(g_hist)[j] = make_uint4(0,0,0,0);
}

// ------ K3: collect candidates with hbin <= thr, 16 rois/thread ------
__global__ void k3_collect(int ngrp16, int n) {
    int g = blockIdx.x*blockDim.x + threadIdx.x;
    if (g >= ngrp16) return;
    int base = g * 16;
    uint4 v[4];
    #pragma unroll
    for (int p = 0; p < 4; p++)
        v[p] = reinterpret_cast<const uint4*>(g_keys)[g*4 + p];
    int thr = g_thrbin;
    #pragma unroll
    for (int p = 0; p < 4; p++) {
        unsigned int kk[4] = {v[p].x, v[p].y, v[p].z, v[p].w};
        #pragma unroll
        for (int l = 0; l < 4; l++) {
            unsigned int key = kk[l];
            int i = base + p*4 + l;
            if (key != 0xFFFFFFFFu && i < n) {
                float m = __uint_as_float(~key);
                if (hist_bin(m) <= thr) {
                    unsigned int pos = atomicAdd(&g_count, 1u);
                    if (pos < CAP) {
                        g_cand[pos] = (((unsigned long long)key) << 32) |
                                      (unsigned int)i;
                    }
                }
            }
        }
    }
}

// ---------- K4a: multi-block rank-sort -> g_skey[0..min(M,300)) ----------
#define K4AB 32
#define K4AT 256

__global__ void k4a_rank() {
    __shared__ unsigned long long keys[CAP];   // 48KB
    int tid = threadIdx.x;
    int M = (int)min(g_count, (unsigned int)CAP);

    for (int t = tid; t < M; t += K4AT) keys[t] = g_cand[t];
    __syncthreads();

    int chunk = (M + K4AB - 1) / K4AB;
    int idx = blockIdx.x * chunk + tid;
    if (tid < chunk && idx < M) {
        unsigned long long k = keys[idx];
        int r = 0;
        for (int j = 0; j < M; j++) r += (keys[j] < k);
        if (r < MAXC) g_skey[r] = k;
    }
    if (blockIdx.x == 0 && tid == 0) g_K = min(M, MAXC);
}

// -- K4b: multi-block decode+bitmatrix; LAST BLOCK: walk + output + reset --
#define K4BB 3
#define K4BT 512

__global__ void __launch_bounds__(K4BT) k4b_final(
    const float* __restrict__ cls,
    const float* __restrict__ bbox,
    const float* __restrict__ rois,
    const float* __restrict__ iminfo,
    float* __restrict__ out)
{
    __shared__ float bx[MAXC][4];
    __shared__ float pr[MAXC][5];
    __shared__ float area[MAXC];
    __shared__ unsigned long long srm[MAXC * NW];
    __shared__ int kept[TOPN];
    __shared__ int nkept;

    int tid = threadIdx.x;
    int K = g_K;
    float W = iminfo[1] - 1.0f, H = iminfo[0] - 1.0f;

    // every block decodes all K boxes (gathers are L2-hot after 1st block)
    if (tid < K) {
        int t = tid;
        int i = (int)(unsigned int)(g_skey[t] & 0xFFFFFFFFULL);
        const float* c = cls + (size_t)i*5;
        float c0=c[0], c1=c[1], c2=c[2], c3=c[3], c4=c[4];
        pr[t][0]=c0; pr[t][1]=c1; pr[t][2]=c2; pr[t][3]=c3; pr[t][4]=c4;
        float m = c1; int a = 1;
        if (c2 > m) { m = c2; a = 2; }
        if (c3 > m) { m = c3; a = 3; }
        if (c4 > m) { m = c4; a = 4; }
        float4 d = *reinterpret_cast<const float4*>(bbox + (size_t)i*20 + a*4);
        float bx1, by1, bx2, by2;
        decode_core(rois[(size_t)i*5+1], rois[(size_t)i*5+2],
                    rois[(size_t)i*5+3], rois[(size_t)i*5+4],
                    d, W, H, bx1, by1, bx2, by2);
        bx[t][0]=bx1; bx[t][1]=by1; bx[t][2]=bx2; bx[t][3]=by2;
        area[t] = (bx2 - bx1) * (by2 - by1);
    }
    __syncthreads();

    // bitmatrix strip: (row, word) tasks, <=64 IoUs each, spread over blocks
    for (int task = blockIdx.x*K4BT + tid; task < K*NW; task += K4BB*K4BT) {
        int i = task / NW;
        int w = task % NW;
        float ax1=bx[i][0], ay1=bx[i][1], ax2=bx[i][2], ay2=bx[i][3], aa=area[i];
        unsigned long long bits = 0ULL;
        int j0 = max(i + 1, w*64);
        int j1 = min(K, w*64 + 64);
        for (int j = j0; j < j1; j++) {
            float4 b4 = *reinterpret_cast<const float4*>(&bx[j][0]);
            float lx = fmaxf(ax1, b4.x);
            float ly = fmaxf(ay1, b4.y);
            float rx = fminf(ax2, b4.z);
            float ry = fminf(ay2, b4.w);
            float iw = fmaxf(rx - lx, 0.0f);
            float ih = fmaxf(ry - ly, 0.0f);
            float inter = iw * ih;
            float iou = inter / (aa + area[j] - inter);
            if (iou > 0.5f) bits |= 1ULL << (j - w*64);
        }
        g_rm[task] = bits;
    }

    // ---- last-block: walk + output + reset ----
    __shared__ bool is_last;
    __threadfence();
    __syncthreads();
    if (tid == 0)
        is_last = (atomicAdd(&g_blkdone2, 1u) == gridDim.x - 1);
    __syncthreads();
    if (!is_last) return;

    for (int t = tid; t < K*NW; t += K4BT) srm[t] = g_rm[t];
    __syncthreads();

    if (tid == 0) {
        unsigned long long sup1=0, sup2=0, sup3=0, sup4=0;
        int cnt = 0;

        #define WALK_WORD(WD, SUPIN, ORS)                                     \
        if (cnt < TOPN && K > (WD)*64) {                                      \
            int nb = K - (WD)*64; if (nb > 64) nb = 64;                       \
            unsigned long long alive =                                        \
                ((nb >= 64) ? ~0ULL : ((1ULL << nb) - 1ULL)) & ~(SUPIN);      \
            while (alive && cnt < TOPN) {                                     \
                int b = __ffsll((long long)alive) - 1;                        \
                int i = (WD)*64 + b;                                          \
                kept[cnt++] = i;                                              \
                alive &= ~srm[i*NW + (WD)];                                   \
                alive &= ~(1ULL << b);                                        \
                ORS                                                           \
            }                                                                 \
        }

        WALK_WORD(0, 0ULL,
            { sup1 |= srm[i*NW+1]; sup2 |= srm[i*NW+2];
              sup3 |= srm[i*NW+3]; sup4 |= srm[i*NW+4]; })
        WALK_WORD(1, sup1,
            { sup2 |= srm[i*NW+2]; sup3 |= srm[i*NW+3]; sup4 |= srm[i*NW+4]; })
        WALK_WORD(2, sup2,
            { sup3 |= srm[i*NW+3]; sup4 |= srm[i*NW+4]; })
        WALK_WORD(3, sup3,
            { sup4 |= srm[i*NW+4]; })
        WALK_WORD(4, sup4, { })
        #undef WALK_WORD

        nkept = cnt;
    }
    __syncthreads();

    for (int t = tid; t < TOPN*10; t += K4BT) out[t] = 0.0f;
    __syncthreads();
    int nk = nkept;
    for (int r = tid; r < nk; r += K4BT) {
        int i = kept[r];
        float* o = out + r*10;
        o[0] = 0.0f;
        o[1] = bx[i][0]; o[2] = bx[i][1]; o[3] = bx[i][2]; o[4] = bx[i][3];
        o[5] = pr[i][0]; o[6] = pr[i][1]; o[7] = pr[i][2];
        o[8] = pr[i][3]; o[9] = pr[i][4];
    }

    if (tid == 0) { g_count = 0u; g_blkdone2 = 0u; }  // reset for next replay
}

// ---------------- launch ----------------
extern "C" void kernel_launch(void* const* d_in, const int* in_sizes, int n_in,
                              void* d_out, int out_size)
{
    const float* cls    = (const float*)d_in[0];
    const float* bbox   = (const float*)d_in[1];
    const float* rois   = (const float*)d_in[2];
    const float* iminfo = (const float*)d_in[3];
    float* out = (float*)d_out;
    int n = in_sizes[0] / 5;
    if (n > MAXN) n = MAXN;

    int ngrp4  = (n + 3) / 4;
    int ngrp16 = (n + 15) / 16;

    k1_score  <<<(ngrp4 + 255)/256, 256>>>(cls, bbox, rois, iminfo, ngrp4, n);
    k3_collect<<<(ngrp16 + 255)/256, 256>>>(ngrp16, n);
    k4a_rank  <<<K4AB, K4AT>>>();
    k4b_final <<<K4BB, K4BT>>>(cls, bbox, rois, iminfo, out);
}

// round 13
// speedup vs baseline: 2.1242x; 1.0052x over previous
#include <cuda_runtime.h>
#include <cuda_bf16.h>

#define NBINS    2048
#define CAP      6144         // 48KB smem in k4a; M (score ties) ~4000
#define MAXC     300
#define TOPN     100
#define MAXN     1000448
#define NW       5            // ceil(300/64)

// ---- scratch (device globals; zero-init at load; every launch re-zeroes) ----
__device__ unsigned int       g_keys[MAXN];   // ~bits(m); 0xFFFFFFFF invalid
__device__ unsigned int       g_hist[NBINS];
__device__ unsigned int       g_count;
__device__ unsigned int       g_blkdone;      // k1 last-block counter
__device__ unsigned int       g_blkdone2;     // k4b last-block counter
__device__ int                g_thrbin;
__device__ unsigned long long g_cand[CAP];
__device__ int                g_K;
__device__ float4             g_box[MAXC];    // decoded boxes (sorted order)
__device__ float              g_area[MAXC];
__device__ float              g_pr[MAXC][5];
__device__ unsigned long long g_rm[MAXC * NW];

// relative bin: ascending in f = 1-m (descending in score). Ties at m==1 -> bin 0.
__device__ __forceinline__ int hist_bin(float m) {
    float f = 1.0f - m;
    int b = (int)(__float_as_uint(f) >> 19);
    return min(b, NBINS - 1);
}

// ---------------- shared box decode ----------------
__device__ __forceinline__ void decode_core(
    float x1, float y1, float x2, float y2,
    float4 d, float W, float H,
    float& bx1, float& by1, float& bx2, float& by2)
{
    float w  = x2 - x1 + 1.0f;
    float h  = y2 - y1 + 1.0f;
    float cx = x1 + 0.5f*(w - 1.0f);
    float cy = y1 + 0.5f*(h - 1.0f);
    float dx = d.x*0.1f, dy = d.y*0.1f, dw = d.z*0.2f, dh = d.w*0.2f;
    float pcx = dx*w + cx;
    float pcy = dy*h + cy;
    float pw  = expf(dw)*w;
    float ph  = expf(dh)*h;
    bx1 = fminf(fmaxf(pcx - 0.5f*(pw - 1.0f), 0.0f), W);
    by1 = fminf(fmaxf(pcy - 0.5f*(ph - 1.0f), 0.0f), H);
    bx2 = fminf(fmaxf(pcx + 0.5f*(pw - 1.0f), 0.0f), W);
    by2 = fminf(fmaxf(pcy + 0.5f*(ph - 1.0f), 0.0f), H);
}

// ---- K1: 4 rois/thread; smem hist; LAST BLOCK computes threshold + zeroes ----
__global__ void __launch_bounds__(256) k1_score(
    const float* __restrict__ cls,
    const float* __restrict__ bbox,
    const float* __restrict__ rois,
    const float* __restrict__ iminfo,
    int ngrp, int n)
{
    __shared__ unsigned int sh[NBINS];
    int tid = threadIdx.x;

    #pragma unroll
    for (int j = tid; j < NBINS/4; j += 256)
        reinterpret_cast<uint4*>(sh)[j] = make_uint4(0,0,0,0);
    __syncthreads();

    int g = blockIdx.x*blockDim.x + tid;
    if (g < ngrp) {
        int base = g * 4;
        bool full = (base + 4 <= n);

        float c[20], r[20];
        if (full) {
            const float4* c4 = reinterpret_cast<const float4*>(cls)  + (size_t)g*5;
            const float4* r4 = reinterpret_cast<const float4*>(rois) + (size_t)g*5;
            #pragma unroll
            for (int q = 0; q < 5; q++) {
                float4 t = c4[q];
                c[4*q]=t.x; c[4*q+1]=t.y; c[4*q+2]=t.z; c[4*q+3]=t.w;
            }
            #pragma unroll
            for (int q = 0; q < 5; q++) {
                float4 t = r4[q];
                r[4*q]=t.x; r[4*q+1]=t.y; r[4*q+2]=t.z; r[4*q+3]=t.w;
            }
        } else {
            #pragma unroll
            for (int q = 0; q < 4; q++) {
                if (base + q < n) {
                    #pragma unroll
                    for (int e = 0; e < 5; e++) {
                        c[q*5+e] = cls [(size_t)(base+q)*5 + e];
                        r[q*5+e] = rois[(size_t)(base+q)*5 + e];
                    }
                }
            }
        }

        float W = iminfo[1] - 1.0f, H = iminfo[0] - 1.0f;
        unsigned int outk[4];

        #pragma unroll
        for (int q = 0; q < 4; q++) {
            unsigned int key = 0xFFFFFFFFu;
            if (base + q < n) {
                float s0=c[q*5], s1=c[q*5+1], s2=c[q*5+2], s3=c[q*5+3], s4=c[q*5+4];
                float m = s1; int a = 1;
                if (s2 > m) { m = s2; a = 2; }
                if (s3 > m) { m = s3; a = 3; }
                if (s4 > m) { m = s4; a = 4; }
                if ((1.0f - s0 >= 0.2f) && (m > 0.1f)) {
                    float4 d = *reinterpret_cast<const float4*>(
                        bbox + (size_t)(base+q)*20 + a*4);
                    float bx1, by1, bx2, by2;
                    decode_core(r[q*5+1], r[q*5+2], r[q*5+3], r[q*5+4],
                                d, W, H, bx1, by1, bx2, by2);
                    float bw = bx2 - bx1 + 1.0f;
                    float bh = by2 - by1 + 1.0f;
                    if (bw >= 6.0f || bh >= 6.0f) {
                        key = ~__float_as_uint(m);
                        atomicAdd(&sh[hist_bin(m)], 1u);
                    }
                }
            }
            outk[q] = key;
        }

        if (full) {
            *reinterpret_cast<uint4*>(g_keys + base) =
                make_uint4(outk[0], outk[1], outk[2], outk[3]);
        } else {
            #pragma unroll
            for (int q = 0; q < 4; q++)
                if (base + q < n) g_keys[base + q] = outk[q];
        }
    }
    __syncthreads();

    #pragma unroll
    for (int j = tid; j < NBINS; j += 256) {
        unsigned int v = sh[j];
        if (v) atomicAdd(&g_hist[j], v);
    }

    // ---- last-block: threshold scan + hist zero ----
    __shared__ bool is_last;
    __threadfence();
    if (tid == 0)
        is_last = (atomicAdd(&g_blkdone, 1u) == gridDim.x - 1);
    __syncthreads();
    if (!is_last) return;

    __shared__ unsigned int part[256];
    {
        unsigned int s = 0;
        #pragma unroll
        for (int j = 0; j < NBINS/256; j++) s += g_hist[tid*(NBINS/256) + j];
        part[tid] = s;
    }
    __syncthreads();
    if (tid == 0) {
        unsigned int cum = 0;
        int thr = NBINS - 1;
        for (int cch = 0; cch < 256; cch++) {
            if (cum + part[cch] >= (unsigned)MAXC) {
                int lo = cch * (NBINS/256);
                for (int b = lo; b < lo + (NBINS/256); b++) {
                    cum += g_hist[b];
                    if (cum >= (unsigned)MAXC) { thr = b; break; }
                }
                break;
            }
            cum += part[cch];
        }
        g_thrbin = thr;
        g_blkdone = 0u;
    }
    __syncthreads();
    #pragma unroll
    for (int j = tid; j < NBINS/4; j += 256)
        reinterpret_cast<uint4*>(g_hist)[j] = make_uint4(0,0,0,0);
}

// ------ K3: collect candidates with hbin <= thr, 16 rois/thread ------
__global__ void k3_collect(int ngrp16, int n) {
    int g = blockIdx.x*blockDim.x + threadIdx.x;
    if (g >= ngrp16) return;
    int base = g * 16;
    uint4 v[4];
    #pragma unroll
    for (int p = 0; p < 4; p++)
        v[p] = reinterpret_cast<const uint4*>(g_keys)[g*4 + p];
    int thr = g_thrbin;
    #pragma unroll
    for (int p = 0; p < 4; p++) {
        unsigned int kk[4] = {v[p].x, v[p].y, v[p].z, v[p].w};
        #pragma unroll
        for (int l = 0; l < 4; l++) {
            unsigned int key = kk[l];
            int i = base + p*4 + l;
            if (key != 0xFFFFFFFFu && i < n) {
                float m = __uint_as_float(~key);
                if (hist_bin(m) <= thr) {
                    unsigned int pos = atomicAdd(&g_count, 1u);
                    if (pos < CAP) {
                        g_cand[pos] = (((unsigned long long)key) << 32) |
                                      (unsigned int)i;
                    }
                }
            }
        }
    }
}

// -- K4a: multi-block rank-sort; ranked threads ALSO decode -> g_box/g_pr --
#define K4AB 64
#define K4AT 256

__global__ void __launch_bounds__(K4AT) k4a_rank(
    const float* __restrict__ cls,
    const float* __restrict__ bbox,
    const float* __restrict__ rois,
    const float* __restrict__ iminfo)
{
    __shared__ unsigned long long keys[CAP];   // 48KB
    int tid = threadIdx.x;
    int M = (int)min(g_count, (unsigned int)CAP);

    for (int t = tid; t < M; t += K4AT) keys[t] = g_cand[t];
    __syncthreads();

    int chunk = (M + K4AB - 1) / K4AB;         // <=96 for CAP=6144
    int idx = blockIdx.x * chunk + tid;
    if (tid < chunk && idx < M) {
        unsigned long long k = keys[idx];
        int r = 0;
        for (int j = 0; j < M; j++) r += (keys[j] < k);
        if (r < MAXC) {
            // this thread owns sorted slot r: decode now (spread across blocks)
            int i = (int)(unsigned int)(k & 0xFFFFFFFFULL);
            const float* c = cls + (size_t)i*5;
            float c0=c[0], c1=c[1], c2=c[2], c3=c[3], c4=c[4];
            g_pr[r][0]=c0; g_pr[r][1]=c1; g_pr[r][2]=c2;
            g_pr[r][3]=c3; g_pr[r][4]=c4;
            float m = c1; int a = 1;
            if (c2 > m) { m = c2; a = 2; }
            if (c3 > m) { m = c3; a = 3; }
            if (c4 > m) { m = c4; a = 4; }
            float4 d = *reinterpret_cast<const float4*>(bbox + (size_t)i*20 + a*4);
            float W = iminfo[1] - 1.0f, H = iminfo[0] - 1.0f;
            float bx1, by1, bx2, by2;
            decode_core(rois[(size_t)i*5+1], rois[(size_t)i*5+2],
                        rois[(size_t)i*5+3], rois[(size_t)i*5+4],
                        d, W, H, bx1, by1, bx2, by2);
            g_box[r]  = make_float4(bx1, by1, bx2, by2);
            g_area[r] = (bx2 - bx1) * (by2 - by1);
        }
    }
    if (blockIdx.x == 0 && tid == 0) g_K = min(M, MAXC);
}

// -- K4b: 148-block bitmatrix strips; LAST BLOCK: walk + output + reset --
#define K4BB 148
#define K4BT 256

__global__ void __launch_bounds__(K4BT) k4b_final(float* __restrict__ out)
{
    __shared__ float4 bx4[MAXC];
    __shared__ float  area[MAXC];
    __shared__ unsigned long long srm[MAXC * NW];
    __shared__ int kept[TOPN];
    __shared__ int nkept;

    int tid = threadIdx.x;
    int K = g_K;

    // broadcast-load decoded boxes (6KB, L2-hot)
    for (int t = tid; t < K; t += K4BT) {
        bx4[t]  = g_box[t];
        area[t] = g_area[t];
    }
    __syncthreads();

    // strip tasks: one per thread, striped across blocks (<=11 per block)
    for (int task = blockIdx.x + K4BB * tid; task < K * NW; task += K4BB * K4BT) {
        int i = task / NW;
        int w = task % NW;
        float4 a4 = bx4[i];
        float aa = area[i];
        unsigned long long bits = 0ULL;
        int j0 = max(i + 1, w*64);
        int j1 = min(K, w*64 + 64);
        for (int j = j0; j < j1; j++) {
            float4 b4 = bx4[j];
            float lx = fmaxf(a4.x, b4.x);
            float ly = fmaxf(a4.y, b4.y);
            float rx = fminf(a4.z, b4.z);
            float ry = fminf(a4.w, b4.w);
            float iw = fmaxf(rx - lx, 0.0f);
            float ih = fmaxf(ry - ly, 0.0f);
            float inter = iw * ih;
            float iou = inter / (aa + area[j] - inter);
            if (iou > 0.5f) bits |= 1ULL << (j - w*64);
        }
        g_rm[task] = bits;
    }

    // ---- last-block: walk + output + reset ----
    __shared__ bool is_last;
    __threadfence();
    __syncthreads();
    if (tid == 0)
        is_last = (atomicAdd(&g_blkdone2, 1u) == gridDim.x - 1);
    __syncthreads();
    if (!is_last) return;

    for (int t = tid; t < K*NW; t += K4BT) srm[t] = g_rm[t];
    __syncthreads();

    if (tid == 0) {
        unsigned long long sup1=0, sup2=0, sup3=0, sup4=0;
        int cnt = 0;

        #define WALK_WORD(WD, SUPIN, ORS)                                     \
        if (cnt < TOPN && K > (WD)*64) {                                      \
            int nb = K - (WD)*64; if (nb > 64) nb = 64;                       \
            unsigned long long alive =                                        \
                ((nb >= 64) ? ~0ULL : ((1ULL << nb) - 1ULL)) & ~(SUPIN);      \
            while (alive && cnt < TOPN) {                                     \
                int b = __ffsll((long long)alive) - 1;                        \
                int i = (WD)*64 + b;                                          \
                kept[cnt++] = i;                                              \
                alive &= ~srm[i*NW + (WD)];                                   \
                alive &= ~(1ULL << b);                                        \
                ORS                                                           \
            }                                                                 \
        }

        WALK_WORD(0, 0ULL,
            { sup1 |= srm[i*NW+1]; sup2 |= srm[i*NW+2];
              sup3 |= srm[i*NW+3]; sup4 |= srm[i*NW+4]; })
        WALK_WORD(1, sup1,
            { sup2 |= srm[i*NW+2]; sup3 |= srm[i*NW+3]; sup4 |= srm[i*NW+4]; })
        WALK_WORD(2, sup2,
            { sup3 |= srm[i*NW+3]; sup4 |= srm[i*NW+4]; })
        WALK_WORD(3, sup3,
            { sup4 |= srm[i*NW+4]; })
        WALK_WORD(4, sup4, { })
        #undef WALK_WORD

        nkept = cnt;
    }
    __syncthreads();

    for (int t = tid; t < TOPN*10; t += K4BT) out[t] = 0.0f;
    __syncthreads();
    int nk = nkept;
    for (int r = tid; r < nk; r += K4BT) {
        int i = kept[r];
        float4 b = bx4[i];
        float* o = out + r*10;
        o[0] = 0.0f;
        o[1] = b.x; o[2] = b.y; o[3] = b.z; o[4] = b.w;
        o[5] = g_pr[i][0]; o[6] = g_pr[i][1]; o[7] = g_pr[i][2];
        o[8] = g_pr[i][3]; o[9] = g_pr[i][4];
    }

    if (tid == 0) { g_count = 0u; g_blkdone2 = 0u; }  // reset for next replay
}

// ---------------- launch ----------------
extern "C" void kernel_launch(void* const* d_in, const int* in_sizes, int n_in,
                              void* d_out, int out_size)
{
    const float* cls    = (const float*)d_in[0];
    const float* bbox   = (const float*)d_in[1];
    const float* rois   = (const float*)d_in[2];
    const float* iminfo = (const float*)d_in[3];
    float* out = (float*)d_out;
    int n = in_sizes[0] / 5;
    if (n > MAXN) n = MAXN;

    int ngrp4  = (n + 3) / 4;
    int ngrp16 = (n + 15) / 16;

    k1_score  <<<(ngrp4 + 255)/256, 256>>>(cls, bbox, rois, iminfo, ngrp4, n);
    k3_collect<<<(ngrp16 + 255)/256, 256>>>(ngrp16, n);
    k4a_rank  <<<K4AB, K4AT>>>(cls, bbox, rois, iminfo);
    k4b_final <<<K4BB, K4BT>>>(out);
}

// round 14
// speedup vs baseline: 2.1873x; 1.0297x over previous
#include <cuda_runtime.h>
#include <cuda_bf16.h>

#define NBINS    2048
#define CAP      6144         // 48KB smem key cache; M (score ties) ~4000
#define MAXC     300
#define TOPN     100
#define MAXN     1000448
#define NW       5            // ceil(300/64)

#define SELB     148          // fused-tail blocks (1 per SM, co-resident)
#define SELT     256

// ---- scratch (device globals; zero-init at load; every launch re-zeroes) ----
__device__ unsigned int       g_keys[MAXN];   // ~bits(m); 0xFFFFFFFF invalid
__device__ unsigned int       g_hist[NBINS];
__device__ unsigned int       g_count;
__device__ unsigned int       g_blkdone;      // k1 last-block counter
__device__ unsigned int       g_bar1, g_bar2, g_done;  // fused-tail barriers
__device__ int                g_thrbin;
__device__ unsigned long long g_cand[CAP];
__device__ float4             g_box[MAXC];
__device__ float              g_area[MAXC];
__device__ float              g_pr[MAXC][5];
__device__ unsigned long long g_rm[MAXC * NW];

// relative bin: ascending in f = 1-m (descending in score). Ties at m==1 -> bin 0.
__device__ __forceinline__ int hist_bin(float m) {
    float f = 1.0f - m;
    int b = (int)(__float_as_uint(f) >> 19);
    return min(b, NBINS - 1);
}

__device__ __forceinline__ void decode_core(
    float x1, float y1, float x2, float y2,
    float4 d, float W, float H,
    float& bx1, float& by1, float& bx2, float& by2)
{
    float w  = x2 - x1 + 1.0f;
    float h  = y2 - y1 + 1.0f;
    float cx = x1 + 0.5f*(w - 1.0f);
    float cy = y1 + 0.5f*(h - 1.0f);
    float dx = d.x*0.1f, dy = d.y*0.1f, dw = d.z*0.2f, dh = d.w*0.2f;
    float pcx = dx*w + cx;
    float pcy = dy*h + cy;
    float pw  = expf(dw)*w;
    float ph  = expf(dh)*h;
    bx1 = fminf(fmaxf(pcx - 0.5f*(pw - 1.0f), 0.0f), W);
    by1 = fminf(fmaxf(pcy - 0.5f*(ph - 1.0f), 0.0f), H);
    bx2 = fminf(fmaxf(pcx + 0.5f*(pw - 1.0f), 0.0f), W);
    by2 = fminf(fmaxf(pcy + 0.5f*(ph - 1.0f), 0.0f), H);
}

// ---- K1: 4 rois/thread; smem hist; LAST BLOCK computes threshold + zeroes ----
__global__ void __launch_bounds__(256) k1_score(
    const float* __restrict__ cls,
    const float* __restrict__ bbox,
    const float* __restrict__ rois,
    const float* __restrict__ iminfo,
    int ngrp, int n)
{
    __shared__ unsigned int sh[NBINS];
    int tid = threadIdx.x;

    #pragma unroll
    for (int j = tid; j < NBINS/4; j += 256)
        reinterpret_cast<uint4*>(sh)[j] = make_uint4(0,0,0,0);
    __syncthreads();

    int g = blockIdx.x*blockDim.x + tid;
    if (g < ngrp) {
        int base = g * 4;
        bool full = (base + 4 <= n);

        float c[20], r[20];
        if (full) {
            const float4* c4 = reinterpret_cast<const float4*>(cls)  + (size_t)g*5;
            const float4* r4 = reinterpret_cast<const float4*>(rois) + (size_t)g*5;
            #pragma unroll
            for (int q = 0; q < 5; q++) {
                float4 t = c4[q];
                c[4*q]=t.x; c[4*q+1]=t.y; c[4*q+2]=t.z; c[4*q+3]=t.w;
            }
            #pragma unroll
            for (int q = 0; q < 5; q++) {
                float4 t = r4[q];
                r[4*q]=t.x; r[4*q+1]=t.y; r[4*q+2]=t.z; r[4*q+3]=t.w;
            }
        } else {
            #pragma unroll
            for (int q = 0; q < 4; q++) {
                if (base + q < n) {
                    #pragma unroll
                    for (int e = 0; e < 5; e++) {
                        c[q*5+e] = cls [(size_t)(base+q)*5 + e];
                        r[q*5+e] = rois[(size_t)(base+q)*5 + e];
                    }
                }
            }
        }

        float W = iminfo[1] - 1.0f, H = iminfo[0] - 1.0f;
        unsigned int outk[4];

        #pragma unroll
        for (int q = 0; q < 4; q++) {
            unsigned int key = 0xFFFFFFFFu;
            if (base + q < n) {
                float s0=c[q*5], s1=c[q*5+1], s2=c[q*5+2], s3=c[q*5+3], s4=c[q*5+4];
                float m = s1; int a = 1;
                if (s2 > m) { m = s2; a = 2; }
                if (s3 > m) { m = s3; a = 3; }
                if (s4 > m) { m = s4; a = 4; }
                if ((1.0f - s0 >= 0.2f) && (m > 0.1f)) {
                    float4 d = *reinterpret_cast<const float4*>(
                        bbox + (size_t)(base+q)*20 + a*4);
                    float bx1, by1, bx2, by2;
                    decode_core(r[q*5+1], r[q*5+2], r[q*5+3], r[q*5+4],
                                d, W, H, bx1, by1, bx2, by2);
                    float bw = bx2 - bx1 + 1.0f;
                    float bh = by2 - by1 + 1.0f;
                    if (bw >= 6.0f || bh >= 6.0f) {
                        key = ~__float_as_uint(m);
                        atomicAdd(&sh[hist_bin(m)], 1u);
                    }
                }
            }
            outk[q] = key;
        }

        if (full) {
            *reinterpret_cast<uint4*>(g_keys + base) =
                make_uint4(outk[0], outk[1], outk[2], outk[3]);
        } else {
            #pragma unroll
            for (int q = 0; q < 4; q++)
                if (base + q < n) g_keys[base + q] = outk[q];
        }
    }
    __syncthreads();

    #pragma unroll
    for (int j = tid; j < NBINS; j += 256) {
        unsigned int v = sh[j];
        if (v) atomicAdd(&g_hist[j], v);
    }

    // ---- last-block: threshold scan + hist zero ----
    __shared__ bool is_last;
    __threadfence();
    if (tid == 0)
        is_last = (atomicAdd(&g_blkdone, 1u) == gridDim.x - 1);
    __syncthreads();
    if (!is_last) return;

    __shared__ unsigned int part[256];
    {
        unsigned int s = 0;
        #pragma unroll
        for (int j = 0; j < NBINS/256; j++) s += g_hist[tid*(NBINS/256) + j];
        part[tid] = s;
    }
    __syncthreads();
    if (tid == 0) {
        unsigned int cum = 0;
        int thr = NBINS - 1;
        for (int cch = 0; cch < 256; cch++) {
            if (cum + part[cch] >= (unsigned)MAXC) {
                int lo = cch * (NBINS/256);
                for (int b = lo; b < lo + (NBINS/256); b++) {
                    cum += g_hist[b];
                    if (cum >= (unsigned)MAXC) { thr = b; break; }
                }
                break;
            }
            cum += part[cch];
        }
        g_thrbin = thr;
        g_blkdone = 0u;
    }
    __syncthreads();
    #pragma unroll
    for (int j = tid; j < NBINS/4; j += 256)
        reinterpret_cast<uint4*>(g_hist)[j] = make_uint4(0,0,0,0);
}

// grid barrier: all SELB blocks co-resident (1 per SM) => spin is safe
__device__ __forceinline__ void grid_bar(unsigned int* ctr, int tid) {
    __syncthreads();
    if (tid == 0) {
        __threadfence();
        atomicAdd(ctr, 1u);
        while (atomicAdd(ctr, 0u) < (unsigned)SELB) { }
    }
    __syncthreads();
}

// ---- K2sel: fused collect + rank/decode + bitmatrix + walk + output ----
__global__ void __launch_bounds__(SELT) k2_sel(
    const float* __restrict__ cls,
    const float* __restrict__ bbox,
    const float* __restrict__ rois,
    const float* __restrict__ iminfo,
    float* __restrict__ out,
    int ngrp16, int n)
{
    // 48KB phase-overlaid shared buffer
    __shared__ __align__(16) unsigned char smraw[49152];
    unsigned long long* skeys = reinterpret_cast<unsigned long long*>(smraw); // phase B
    float4* bx4 = reinterpret_cast<float4*>(smraw);                           // phase C/D
    float*  area = reinterpret_cast<float*>(smraw + 4800);
    unsigned long long* srm = reinterpret_cast<unsigned long long*>(smraw + 6144);
    int* kept = reinterpret_cast<int*>(smraw + 6144 + 12000);

    int tid  = threadIdx.x;
    int lane = tid & 31;
    int wid  = tid >> 5;

    // ---------- Phase A: collect candidates ----------
    int thr = g_thrbin;
    for (int g = blockIdx.x*SELT + tid; g < ngrp16; g += SELB*SELT) {
        int base = g * 16;
        uint4 v[4];
        #pragma unroll
        for (int p = 0; p < 4; p++)
            v[p] = reinterpret_cast<const uint4*>(g_keys)[g*4 + p];
        #pragma unroll
        for (int p = 0; p < 4; p++) {
            unsigned int kk[4] = {v[p].x, v[p].y, v[p].z, v[p].w};
            #pragma unroll
            for (int l = 0; l < 4; l++) {
                unsigned int key = kk[l];
                int i = base + p*4 + l;
                if (key != 0xFFFFFFFFu && i < n) {
                    float m = __uint_as_float(~key);
                    if (hist_bin(m) <= thr) {
                        unsigned int pos = atomicAdd(&g_count, 1u);
                        if (pos < CAP)
                            g_cand[pos] = (((unsigned long long)key) << 32) |
                                          (unsigned int)i;
                    }
                }
            }
        }
    }
    grid_bar(&g_bar1, tid);

    // ---------- Phase B: rank + decode ----------
    int M = (int)min(g_count, (unsigned int)CAP);
    int K = min(M, MAXC);
    for (int t = tid; t < M; t += SELT) skeys[t] = g_cand[t];
    __syncthreads();

    int chunk = (M + SELB - 1) / SELB;          // keys per block
    int kbase = blockIdx.x * chunk;
    int kend  = min(kbase + chunk, M);
    float W = iminfo[1] - 1.0f, H = iminfo[0] - 1.0f;
    for (int kk = kbase + wid; kk < kend; kk += SELT/32) {
        unsigned long long key = skeys[kk];
        int r = 0;
        for (int j = lane; j < M; j += 32) r += (skeys[j] < key);
        r = __reduce_add_sync(0xFFFFFFFFu, r);
        if (r < MAXC && lane == 0) {
            int i = (int)(unsigned int)(key & 0xFFFFFFFFULL);
            const float* c = cls + (size_t)i*5;
            float c0=c[0], c1=c[1], c2=c[2], c3=c[3], c4=c[4];
            g_pr[r][0]=c0; g_pr[r][1]=c1; g_pr[r][2]=c2;
            g_pr[r][3]=c3; g_pr[r][4]=c4;
            float m = c1; int a = 1;
            if (c2 > m) { m = c2; a = 2; }
            if (c3 > m) { m = c3; a = 3; }
            if (c4 > m) { m = c4; a = 4; }
            float4 d = *reinterpret_cast<const float4*>(bbox + (size_t)i*20 + a*4);
            float bx1, by1, bx2, by2;
            decode_core(rois[(size_t)i*5+1], rois[(size_t)i*5+2],
                        rois[(size_t)i*5+3], rois[(size_t)i*5+4],
                        d, W, H, bx1, by1, bx2, by2);
            g_box[r]  = make_float4(bx1, by1, bx2, by2);
            g_area[r] = (bx2 - bx1) * (by2 - by1);
        }
    }
    grid_bar(&g_bar2, tid);

    // ---------- Phase C: bitmatrix strips ----------
    for (int t = tid; t < K; t += SELT) {       // smem copy of decoded boxes
        bx4[t]  = g_box[t];
        area[t] = g_area[t];
    }
    __syncthreads();

    for (int task = blockIdx.x*SELT + tid; task < K*NW; task += SELB*SELT) {
        int i = task / NW;
        int w = task % NW;
        float4 a4 = bx4[i];
        float aa = area[i];
        unsigned long long bits = 0ULL;
        int j0 = max(i + 1, w*64);
        int j1 = min(K, w*64 + 64);
        for (int j = j0; j < j1; j++) {
            float4 b4 = bx4[j];
            float lx = fmaxf(a4.x, b4.x);
            float ly = fmaxf(a4.y, b4.y);
            float rx = fminf(a4.z, b4.z);
            float ry = fminf(a4.w, b4.w);
            float iw = fmaxf(rx - lx, 0.0f);
            float ih = fmaxf(ry - ly, 0.0f);
            float inter = iw * ih;
            float iou = inter / (aa + area[j] - inter);
            if (iou > 0.5f) bits |= 1ULL << (j - w*64);
        }
        g_rm[task] = bits;
    }

    // ---------- last block: walk + output + reset ----------
    __shared__ bool is_last;
    __threadfence();
    __syncthreads();
    if (tid == 0)
        is_last = (atomicAdd(&g_done, 1u) == SELB - 1);
    __syncthreads();
    if (!is_last) return;

    for (int t = tid; t < K*NW; t += SELT) srm[t] = g_rm[t];
    __syncthreads();

    __shared__ int nkept;
    if (tid == 0) {
        unsigned long long sup1=0, sup2=0, sup3=0, sup4=0;
        int cnt = 0;

        #define WALK_WORD(WD, SUPIN, ORS)                                     \
        if (cnt < TOPN && K > (WD)*64) {                                      \
            int nb = K - (WD)*64; if (nb > 64) nb = 64;                       \
            unsigned long long alive =                                        \
                ((nb >= 64) ? ~0ULL : ((1ULL << nb) - 1ULL)) & ~(SUPIN);      \
            while (alive && cnt < TOPN) {                                     \
                int b = __ffsll((long long)alive) - 1;                        \
                int i = (WD)*64 + b;                                          \
                kept[cnt++] = i;                                              \
                alive &= ~srm[i*NW + (WD)];                                   \
                alive &= ~(1ULL << b);                                        \
                ORS                                                           \
            }                                                                 \
        }

        WALK_WORD(0, 0ULL,
            { sup1 |= srm[i*NW+1]; sup2 |= srm[i*NW+2];
              sup3 |= srm[i*NW+3]; sup4 |= srm[i*NW+4]; })
        WALK_WORD(1, sup1,
            { sup2 |= srm[i*NW+2]; sup3 |= srm[i*NW+3]; sup4 |= srm[i*NW+4]; })
        WALK_WORD(2, sup2,
            { sup3 |= srm[i*NW+3]; sup4 |= srm[i*NW+4]; })
        WALK_WORD(3, sup3,
            { sup4 |= srm[i*NW+4]; })
        WALK_WORD(4, sup4, { })
        #undef WALK_WORD

        nkept = cnt;
    }
    __syncthreads();

    for (int t = tid; t < TOPN*10; t += SELT) out[t] = 0.0f;
    __syncthreads();
    int nk = nkept;
    for (int r = tid; r < nk; r += SELT) {
        int i = kept[r];
        float4 b = bx4[i];
        float* o = out + r*10;
        o[0] = 0.0f;
        o[1] = b.x; o[2] = b.y; o[3] = b.z; o[4] = b.w;
        o[5] = g_pr[i][0]; o[6] = g_pr[i][1]; o[7] = g_pr[i][2];
        o[8] = g_pr[i][3]; o[9] = g_pr[i][4];
    }

    if (tid == 0) {   // reset all tail state for next graph replay
        g_count = 0u; g_bar1 = 0u; g_bar2 = 0u; g_done = 0u;
    }
}

// ---------------- launch ----------------
extern "C" void kernel_launch(void* const* d_in, const int* in_sizes, int n_in,
                              void* d_out, int out_size)
{
    const float* cls    = (const float*)d_in[0];
    const float* bbox   = (const float*)d_in[1];
    const float* rois   = (const float*)d_in[2];
    const float* iminfo = (const float*)d_in[3];
    float* out = (float*)d_out;
    int n = in_sizes[0] / 5;
    if (n > MAXN) n = MAXN;

    int ngrp4  = (n + 3) / 4;
    int ngrp16 = (n + 15) / 16;

    k1_score<<<(ngrp4 + 255)/256, 256>>>(cls, bbox, rois, iminfo, ngrp4, n);
    k2_sel  <<<SELB, SELT>>>(cls, bbox, rois, iminfo, out, ngrp16, n);
}